// round 12
// baseline (speedup 1.0000x reference)
#include <cuda_runtime.h>
#include <cuda_fp16.h>

#define NN 100000
#define EE 1600000
#define FIN 128
#define HID 64

// ---- scratch (static __device__ — no allocation) ----
__device__ __align__(16) __half2 g_h1h[NN * 32];  // h1, fp16, feature pairs (128B/row)
__device__ __align__(16) __half2 g_h2h[NN * 32];  // h2, fp16
__device__ __align__(16) float g_as1[NN * 4];
__device__ __align__(16) float g_ad1[NN * 4];
__device__ __align__(16) float g_agg1[NN * HID];
__device__ __align__(16) float g_as2[NN];
__device__ __align__(16) float g_ad2[NN];
__device__ int g_cnt[NN];    // degree by dst (zero at load; re-zeroed by agg2f each call)
__device__ int g_rs[NN];     // CSR row starts (unordered ranges)
__device__ int g_cur[NN];    // fill cursors
__device__ int g_srcs[EE];   // CSR: src per incident edge, grouped by dst
__device__ int g_total;      // range-allocation cursor (reset by k_fill each call)

__device__ __forceinline__ float lrelu(float t) { return fmaxf(t, 0.2f * t); }

// ---------------- layer-1 GEMM (+ fused degree histogram) ----------------
// 128 threads = 4 warps, 8 rows/warp (3125*32 == NN exactly).
// Per k: 2x LDS.128 (x, broadcast) + 1x LDS.64 (W) + 16 FFMA.
__global__ void k_gemm1h(const float* __restrict__ x, const float* __restrict__ W1,
                         const float* __restrict__ a_src, const float* __restrict__ a_dst,
                         const int* __restrict__ ei) {
    __shared__ float2 Wsh[FIN * 32];   // 32 KB
    __shared__ float4 XA[4][FIN];      // 8 KB: rows r0..r0+3
    __shared__ float4 XB[4][FIN];      // 8 KB: rows r0+4..r0+7
    int tid = threadIdx.x;

    // fused histogram: exactly 4 edges per thread (3125*128*4 == EE)
    {
        int e0 = blockIdx.x * 128 + tid;
#pragma unroll
        for (int t = 0; t < 4; t++)
            atomicAdd(&g_cnt[__ldg(&ei[EE + e0 + t * 400000])], 1);
    }

    for (int i = tid; i < FIN * 32; i += 128) Wsh[i] = ((const float2*)W1)[i];

    int lane = tid & 31, w = tid >> 5;
    int r0 = (blockIdx.x * 4 + w) * 8;

#pragma unroll
    for (int j = 0; j < 4; j++) {
        int k = 32 * j + lane;
        float4 va, vb;
        va.x = x[(r0 + 0) * FIN + k];
        va.y = x[(r0 + 1) * FIN + k];
        va.z = x[(r0 + 2) * FIN + k];
        va.w = x[(r0 + 3) * FIN + k];
        vb.x = x[(r0 + 4) * FIN + k];
        vb.y = x[(r0 + 5) * FIN + k];
        vb.z = x[(r0 + 6) * FIN + k];
        vb.w = x[(r0 + 7) * FIN + k];
        XA[w][k] = va;
        XB[w][k] = vb;
    }
    __syncthreads();

    float acc0[8] = {}, acc1[8] = {};
#pragma unroll 16
    for (int k = 0; k < FIN; k++) {
        float4 xa = XA[w][k];
        float4 xb = XB[w][k];
        float2 wv = Wsh[k * 32 + lane];
        acc0[0] += xa.x * wv.x;  acc1[0] += xa.x * wv.y;
        acc0[1] += xa.y * wv.x;  acc1[1] += xa.y * wv.y;
        acc0[2] += xa.z * wv.x;  acc1[2] += xa.z * wv.y;
        acc0[3] += xa.w * wv.x;  acc1[3] += xa.w * wv.y;
        acc0[4] += xb.x * wv.x;  acc1[4] += xb.x * wv.y;
        acc0[5] += xb.y * wv.x;  acc1[5] += xb.y * wv.y;
        acc0[6] += xb.z * wv.x;  acc1[6] += xb.z * wv.y;
        acc0[7] += xb.w * wv.x;  acc1[7] += xb.w * wv.y;
    }

    float s0 = __ldg(&a_src[2 * lane]), s1 = __ldg(&a_src[2 * lane + 1]);
    float d0 = __ldg(&a_dst[2 * lane]), d1 = __ldg(&a_dst[2 * lane + 1]);

#pragma unroll
    for (int i = 0; i < 8; i++) {
        int row = r0 + i;
        g_h1h[row * 32 + lane] = __floats2half2_rn(acc0[i], acc1[i]);
        float pa = acc0[i] * s0 + acc1[i] * s1;
        float pd = acc0[i] * d0 + acc1[i] * d1;
#pragma unroll
        for (int off = 4; off; off >>= 1) {
            pa += __shfl_xor_sync(0xffffffffu, pa, off);
            pd += __shfl_xor_sync(0xffffffffu, pd, off);
        }
        if ((lane & 7) == 0) {
            g_as1[row * 4 + (lane >> 3)] = pa;
            g_ad1[row * 4 + (lane >> 3)] = pd;
        }
    }
}

// ---------------- CSR range allocation ----------------
__global__ void k_alloc() {
    int i = blockIdx.x * blockDim.x + threadIdx.x;
    int lane = threadIdx.x & 31;
    int c = (i < NN) ? g_cnt[i] : 0;
    int s = c;
#pragma unroll
    for (int off = 1; off < 32; off <<= 1) {
        int t = __shfl_up_sync(0xffffffffu, s, off);
        if (lane >= off) s += t;
    }
    int wtot = __shfl_sync(0xffffffffu, s, 31);
    int base = 0;
    if (lane == 31) base = atomicAdd(&g_total, wtot);
    base = __shfl_sync(0xffffffffu, base, 31);
    if (i < NN) {
        int r = base + s - c;
        g_rs[i] = r;
        g_cur[i] = r;
    }
}

__global__ void k_fill(const int* __restrict__ ei) {
    int e = blockIdx.x * blockDim.x + threadIdx.x;
    if (e == 0) g_total = 0;
    if (e < EE) {
        int s = __ldg(&ei[e]);
        int d = __ldg(&ei[EE + e]);
        int p = atomicAdd(&g_cur[d], 1);
        g_srcs[p] = s;
    }
}

// ---------------- layer-1 gather aggregation (round-11 form) ----------------
__global__ void k_agg1() {
    int n = blockIdx.x * 8 + (threadIdx.x >> 5);
    if (n >= NN) return;
    int lane = threadIdx.x & 31;
    int grp = lane >> 3;
    int q = lane & 7;
    int head = q >> 1;

    int rs = g_rs[n];
    int deg = g_cnt[n];
    float adv = g_ad1[n * 4 + head];

    float a0 = 0.f, a1 = 0.f, a2 = 0.f, a3 = 0.f;
    float a4 = 0.f, a5 = 0.f, a6 = 0.f, a7 = 0.f, den = 0.f;

    const float4* h4 = (const float4*)g_h1h;
    for (int j = 0; j < deg; j += 8) {
        int j0 = j + grp, j1 = j + grp + 4;
        int s0 = g_srcs[rs + (j0 < deg ? j0 : deg - 1)];
        int s1 = g_srcs[rs + (j1 < deg ? j1 : deg - 1)];
        float c0 = g_as1[s0 * 4 + head];
        float c1 = g_as1[s1 * 4 + head];
        float4 r0 = h4[s0 * 8 + q];
        float4 r1 = h4[s1 * 8 + q];
        float e0 = (j0 < deg) ? __expf(lrelu(c0 + adv)) : 0.f;
        float e1 = (j1 < deg) ? __expf(lrelu(c1 + adv)) : 0.f;
        den += e0 + e1;
        const __half2* p0 = (const __half2*)&r0;
        const __half2* p1 = (const __half2*)&r1;
        float2 v;
        v = __half22float2(p0[0]); a0 += e0 * v.x; a1 += e0 * v.y;
        v = __half22float2(p0[1]); a2 += e0 * v.x; a3 += e0 * v.y;
        v = __half22float2(p0[2]); a4 += e0 * v.x; a5 += e0 * v.y;
        v = __half22float2(p0[3]); a6 += e0 * v.x; a7 += e0 * v.y;
        v = __half22float2(p1[0]); a0 += e1 * v.x; a1 += e1 * v.y;
        v = __half22float2(p1[1]); a2 += e1 * v.x; a3 += e1 * v.y;
        v = __half22float2(p1[2]); a4 += e1 * v.x; a5 += e1 * v.y;
        v = __half22float2(p1[3]); a6 += e1 * v.x; a7 += e1 * v.y;
    }
#pragma unroll
    for (int off = 8; off <= 16; off <<= 1) {
        den += __shfl_xor_sync(0xffffffffu, den, off);
        a0 += __shfl_xor_sync(0xffffffffu, a0, off);
        a1 += __shfl_xor_sync(0xffffffffu, a1, off);
        a2 += __shfl_xor_sync(0xffffffffu, a2, off);
        a3 += __shfl_xor_sync(0xffffffffu, a3, off);
        a4 += __shfl_xor_sync(0xffffffffu, a4, off);
        a5 += __shfl_xor_sync(0xffffffffu, a5, off);
        a6 += __shfl_xor_sync(0xffffffffu, a6, off);
        a7 += __shfl_xor_sync(0xffffffffu, a7, off);
    }
    float inv = 1.f / (den + 1e-16f);
    if (grp == 0) {
        float4* dst = (float4*)g_agg1 + n * 16 + q * 2;
        float4 o;
        o.x = a0 * inv; o.y = a1 * inv; o.z = a2 * inv; o.w = a3 * inv;
        dst[0] = o;
        o.x = a4 * inv; o.y = a5 * inv; o.z = a6 * inv; o.w = a7 * inv;
        dst[1] = o;
    }
}

// ---------------- layer-2 GEMM: 4 warps, 8 rows/warp ----------------
__global__ void k_gemm2(const float* __restrict__ W2, const float* __restrict__ b1,
                        const float* __restrict__ a_src, const float* __restrict__ a_dst) {
    __shared__ float2 Wsh[HID * 32];   // 16 KB
    __shared__ float4 XA[4][HID];      // 4 KB
    __shared__ float4 XB[4][HID];      // 4 KB
    int tid = threadIdx.x;
    for (int i = tid; i < HID * 32; i += 128) Wsh[i] = ((const float2*)W2)[i];

    int lane = tid & 31, w = tid >> 5;
    int r0 = (blockIdx.x * 4 + w) * 8;
    float b0 = __ldg(&b1[2 * lane]), b1v = __ldg(&b1[2 * lane + 1]);

    {
        const float2* af2 = (const float2*)g_agg1;
        float2 v0 = af2[(r0 + 0) * 32 + lane];
        float2 v1 = af2[(r0 + 1) * 32 + lane];
        float2 v2 = af2[(r0 + 2) * 32 + lane];
        float2 v3 = af2[(r0 + 3) * 32 + lane];
        float2 v4 = af2[(r0 + 4) * 32 + lane];
        float2 v5 = af2[(r0 + 5) * 32 + lane];
        float2 v6 = af2[(r0 + 6) * 32 + lane];
        float2 v7 = af2[(r0 + 7) * 32 + lane];
        float4 c;
        c.x = fmaxf(v0.x + b0, 0.f); c.y = fmaxf(v1.x + b0, 0.f);
        c.z = fmaxf(v2.x + b0, 0.f); c.w = fmaxf(v3.x + b0, 0.f);
        XA[w][2 * lane] = c;
        c.x = fmaxf(v0.y + b1v, 0.f); c.y = fmaxf(v1.y + b1v, 0.f);
        c.z = fmaxf(v2.y + b1v, 0.f); c.w = fmaxf(v3.y + b1v, 0.f);
        XA[w][2 * lane + 1] = c;
        c.x = fmaxf(v4.x + b0, 0.f); c.y = fmaxf(v5.x + b0, 0.f);
        c.z = fmaxf(v6.x + b0, 0.f); c.w = fmaxf(v7.x + b0, 0.f);
        XB[w][2 * lane] = c;
        c.x = fmaxf(v4.y + b1v, 0.f); c.y = fmaxf(v5.y + b1v, 0.f);
        c.z = fmaxf(v6.y + b1v, 0.f); c.w = fmaxf(v7.y + b1v, 0.f);
        XB[w][2 * lane + 1] = c;
    }
    __syncthreads();

    float acc0[8] = {}, acc1[8] = {};
#pragma unroll 16
    for (int k = 0; k < HID; k++) {
        float4 xa = XA[w][k];
        float4 xb = XB[w][k];
        float2 wv = Wsh[k * 32 + lane];
        acc0[0] += xa.x * wv.x;  acc1[0] += xa.x * wv.y;
        acc0[1] += xa.y * wv.x;  acc1[1] += xa.y * wv.y;
        acc0[2] += xa.z * wv.x;  acc1[2] += xa.z * wv.y;
        acc0[3] += xa.w * wv.x;  acc1[3] += xa.w * wv.y;
        acc0[4] += xb.x * wv.x;  acc1[4] += xb.x * wv.y;
        acc0[5] += xb.y * wv.x;  acc1[5] += xb.y * wv.y;
        acc0[6] += xb.z * wv.x;  acc1[6] += xb.z * wv.y;
        acc0[7] += xb.w * wv.x;  acc1[7] += xb.w * wv.y;
    }

    float s0 = __ldg(&a_src[2 * lane]), s1 = __ldg(&a_src[2 * lane + 1]);
    float d0 = __ldg(&a_dst[2 * lane]), d1 = __ldg(&a_dst[2 * lane + 1]);

#pragma unroll
    for (int i = 0; i < 8; i++) {
        int row = r0 + i;
        g_h2h[row * 32 + lane] = __floats2half2_rn(acc0[i], acc1[i]);
        float pa = acc0[i] * s0 + acc1[i] * s1;
        float pd = acc0[i] * d0 + acc1[i] * d1;
#pragma unroll
        for (int off = 16; off; off >>= 1) {
            pa += __shfl_xor_sync(0xffffffffu, pa, off);
            pd += __shfl_xor_sync(0xffffffffu, pd, off);
        }
        if (lane == 0) {
            g_as2[row] = pa;
            g_ad2[row] = pd;
        }
    }
}

// ---------------- layer-2 gather aggregation fused with final projection (round-11 form) ----------------
__global__ void k_agg2f(const float* __restrict__ b2, const float* __restrict__ Wc,
                        const float* __restrict__ bc, float* __restrict__ out) {
    int n = blockIdx.x * 8 + (threadIdx.x >> 5);
    if (n >= NN) return;
    int lane = threadIdx.x & 31;
    int grp = lane >> 3;
    int q = lane & 7;

    int rs = g_rs[n];
    int deg = g_cnt[n];
    float adv = g_ad2[n];

    float a0 = 0.f, a1 = 0.f, a2 = 0.f, a3 = 0.f;
    float a4 = 0.f, a5 = 0.f, a6 = 0.f, a7 = 0.f, den = 0.f;

    const float4* h4 = (const float4*)g_h2h;
    for (int j = 0; j < deg; j += 8) {
        int j0 = j + grp, j1 = j + grp + 4;
        int s0 = g_srcs[rs + (j0 < deg ? j0 : deg - 1)];
        int s1 = g_srcs[rs + (j1 < deg ? j1 : deg - 1)];
        float c0 = g_as2[s0];
        float c1 = g_as2[s1];
        float4 r0 = h4[s0 * 8 + q];
        float4 r1 = h4[s1 * 8 + q];
        float e0 = (j0 < deg) ? __expf(lrelu(c0 + adv)) : 0.f;
        float e1 = (j1 < deg) ? __expf(lrelu(c1 + adv)) : 0.f;
        den += e0 + e1;
        const __half2* p0 = (const __half2*)&r0;
        const __half2* p1 = (const __half2*)&r1;
        float2 v;
        v = __half22float2(p0[0]); a0 += e0 * v.x; a1 += e0 * v.y;
        v = __half22float2(p0[1]); a2 += e0 * v.x; a3 += e0 * v.y;
        v = __half22float2(p0[2]); a4 += e0 * v.x; a5 += e0 * v.y;
        v = __half22float2(p0[3]); a6 += e0 * v.x; a7 += e0 * v.y;
        v = __half22float2(p1[0]); a0 += e1 * v.x; a1 += e1 * v.y;
        v = __half22float2(p1[1]); a2 += e1 * v.x; a3 += e1 * v.y;
        v = __half22float2(p1[2]); a4 += e1 * v.x; a5 += e1 * v.y;
        v = __half22float2(p1[3]); a6 += e1 * v.x; a7 += e1 * v.y;
    }
#pragma unroll
    for (int off = 8; off <= 16; off <<= 1) {
        den += __shfl_xor_sync(0xffffffffu, den, off);
        a0 += __shfl_xor_sync(0xffffffffu, a0, off);
        a1 += __shfl_xor_sync(0xffffffffu, a1, off);
        a2 += __shfl_xor_sync(0xffffffffu, a2, off);
        a3 += __shfl_xor_sync(0xffffffffu, a3, off);
        a4 += __shfl_xor_sync(0xffffffffu, a4, off);
        a5 += __shfl_xor_sync(0xffffffffu, a5, off);
        a6 += __shfl_xor_sync(0xffffffffu, a6, off);
        a7 += __shfl_xor_sync(0xffffffffu, a7, off);
    }
    float inv = 1.f / (den + 1e-16f);
    float4 ba = ((const float4*)b2)[q * 2],  bb = ((const float4*)b2)[q * 2 + 1];
    float4 wa = ((const float4*)Wc)[q * 2],  wb = ((const float4*)Wc)[q * 2 + 1];
    float v = fmaxf(a0 * inv + ba.x, 0.f) * wa.x
            + fmaxf(a1 * inv + ba.y, 0.f) * wa.y
            + fmaxf(a2 * inv + ba.z, 0.f) * wa.z
            + fmaxf(a3 * inv + ba.w, 0.f) * wa.w
            + fmaxf(a4 * inv + bb.x, 0.f) * wb.x
            + fmaxf(a5 * inv + bb.y, 0.f) * wb.y
            + fmaxf(a6 * inv + bb.z, 0.f) * wb.z
            + fmaxf(a7 * inv + bb.w, 0.f) * wb.w;
#pragma unroll
    for (int off = 1; off <= 4; off <<= 1) v += __shfl_xor_sync(0xffffffffu, v, off);
    if (lane == 0) {
        out[n] = v + __ldg(&bc[0]);
        g_cnt[n] = 0;  // restore invariant for next call's histogram
    }
}

extern "C" void kernel_launch(void* const* d_in, const int* in_sizes, int n_in,
                              void* d_out, int out_size) {
    const float* x      = (const float*)d_in[0];
    const int* ei       = (const int*)d_in[1];   // JAX x64 disabled -> int32
    const float* W1     = (const float*)d_in[2];
    const float* a_src1 = (const float*)d_in[3];
    const float* a_dst1 = (const float*)d_in[4];
    const float* b1     = (const float*)d_in[5];
    const float* W2     = (const float*)d_in[6];
    const float* a_src2 = (const float*)d_in[7];
    const float* a_dst2 = (const float*)d_in[8];
    const float* b2     = (const float*)d_in[9];
    const float* Wc     = (const float*)d_in[10];
    const float* bc     = (const float*)d_in[11];
    float* out          = (float*)d_out;
    (void)in_sizes; (void)n_in; (void)out_size;

    k_gemm1h<<<3125, 128>>>(x, W1, a_src1, a_dst1, ei);  // 1: GEMM1 + degree hist
    k_alloc<<<(NN + 255) / 256, 256>>>();                // 2: CSR range alloc
    k_fill<<<(EE + 255) / 256, 256>>>(ei);               // 3: CSR fill
    k_agg1<<<12500, 256>>>();                            // 4: <- ncu sample
    k_gemm2<<<3125, 128>>>(W2, b1, a_src2, a_dst2);      // 5
    k_agg2f<<<12500, 256>>>(b2, Wc, bc, out);            // 6
}

// round 13
// speedup vs baseline: 1.0014x; 1.0014x over previous
#include <cuda_runtime.h>
#include <cuda_fp16.h>

#define NN 100000
#define EE 1600000
#define FIN 128
#define HID 64

// ---- scratch (static __device__ — no allocation) ----
__device__ __align__(16) __half2 g_h1h[NN * 32];  // h1, fp16, feature pairs (128B/row)
__device__ __align__(16) __half2 g_h2h[NN * 32];  // h2, fp16
__device__ __align__(16) float g_as1[NN * 4];
__device__ __align__(16) float g_ad1[NN * 4];
__device__ __align__(16) float g_agg1[NN * HID];
__device__ __align__(16) float g_as2[NN];
__device__ __align__(16) float g_ad2[NN];
__device__ int g_cnt[NN];    // degree by dst (zero at load; re-zeroed by agg2f each call)
__device__ int g_rs[NN];     // CSR row starts (unordered ranges)
__device__ int g_cur[NN];    // fill cursors
__device__ int g_srcs[EE];   // CSR: src per incident edge, grouped by dst
__device__ int g_total;      // range-allocation cursor (reset by k_fill each call)

__device__ __forceinline__ float lrelu(float t) { return fmaxf(t, 0.2f * t); }

// ---------------- layer-1 GEMM (+ fused degree histogram), round-11 form ----------------
__global__ void k_gemm1h(const float* __restrict__ x, const float* __restrict__ W1,
                         const float* __restrict__ a_src, const float* __restrict__ a_dst,
                         const int* __restrict__ ei) {
    __shared__ float2 Wsh[FIN * 32];      // 32 KB
    __shared__ float4 Xsh[8][FIN];        // 16 KB
    int tid = threadIdx.x;

    // fused histogram: exactly 2 edges per thread (3125*512 == EE)
    {
        int e = blockIdx.x * 512 + tid;
        atomicAdd(&g_cnt[__ldg(&ei[EE + e])], 1);
        atomicAdd(&g_cnt[__ldg(&ei[EE + e + 256])], 1);
    }

    for (int i = tid; i < FIN * 32; i += 256) Wsh[i] = ((const float2*)W1)[i];

    int lane = tid & 31, w = tid >> 5;
    int r0 = (blockIdx.x * 8 + w) * 4;

#pragma unroll
    for (int j = 0; j < 4; j++) {
        float4 v;
        v.x = x[(r0 + 0) * FIN + 32 * j + lane];
        v.y = x[(r0 + 1) * FIN + 32 * j + lane];
        v.z = x[(r0 + 2) * FIN + 32 * j + lane];
        v.w = x[(r0 + 3) * FIN + 32 * j + lane];
        Xsh[w][32 * j + lane] = v;
    }
    __syncthreads();

    float acc0[4] = {}, acc1[4] = {};
#pragma unroll
    for (int k = 0; k < FIN; k++) {
        float4 xv = Xsh[w][k];            // LDS.128 broadcast
        float2 wv = Wsh[k * 32 + lane];   // LDS.64
        acc0[0] += xv.x * wv.x;  acc1[0] += xv.x * wv.y;
        acc0[1] += xv.y * wv.x;  acc1[1] += xv.y * wv.y;
        acc0[2] += xv.z * wv.x;  acc1[2] += xv.z * wv.y;
        acc0[3] += xv.w * wv.x;  acc1[3] += xv.w * wv.y;
    }

    float s0 = __ldg(&a_src[2 * lane]), s1 = __ldg(&a_src[2 * lane + 1]);
    float d0 = __ldg(&a_dst[2 * lane]), d1 = __ldg(&a_dst[2 * lane + 1]);

#pragma unroll
    for (int i = 0; i < 4; i++) {
        int row = r0 + i;
        g_h1h[row * 32 + lane] = __floats2half2_rn(acc0[i], acc1[i]);
        float pa = acc0[i] * s0 + acc1[i] * s1;
        float pd = acc0[i] * d0 + acc1[i] * d1;
#pragma unroll
        for (int off = 4; off; off >>= 1) {
            pa += __shfl_xor_sync(0xffffffffu, pa, off);
            pd += __shfl_xor_sync(0xffffffffu, pd, off);
        }
        if ((lane & 7) == 0) {
            g_as1[row * 4 + (lane >> 3)] = pa;
            g_ad1[row * 4 + (lane >> 3)] = pd;
        }
    }
}

// ---------------- CSR range allocation ----------------
__global__ void k_alloc() {
    int i = blockIdx.x * blockDim.x + threadIdx.x;
    int lane = threadIdx.x & 31;
    int c = (i < NN) ? g_cnt[i] : 0;
    int s = c;
#pragma unroll
    for (int off = 1; off < 32; off <<= 1) {
        int t = __shfl_up_sync(0xffffffffu, s, off);
        if (lane >= off) s += t;
    }
    int wtot = __shfl_sync(0xffffffffu, s, 31);
    int base = 0;
    if (lane == 31) base = atomicAdd(&g_total, wtot);
    base = __shfl_sync(0xffffffffu, base, 31);
    if (i < NN) {
        int r = base + s - c;
        g_rs[i] = r;
        g_cur[i] = r;
    }
}

__global__ void k_fill(const int* __restrict__ ei) {
    int e = blockIdx.x * blockDim.x + threadIdx.x;
    if (e == 0) g_total = 0;
    if (e < EE) {
        int s = __ldg(&ei[e]);
        int d = __ldg(&ei[EE + e]);
        int p = atomicAdd(&g_cur[d], 1);
        g_srcs[p] = s;
    }
}

// ---------------- layer-1 gather aggregation: node-strided warps ----------------
// Grid 1250x256 = 10000 warps, 10 nodes per warp -> balanced CTA runtimes.
__global__ void k_agg1() {
    int lane = threadIdx.x & 31;
    int grp = lane >> 3;
    int q = lane & 7;
    int head = q >> 1;
    int wglob = blockIdx.x * 8 + (threadIdx.x >> 5);
    const int nwarps = 1250 * 8;

    const float4* h4 = (const float4*)g_h1h;

    for (int n = wglob; n < NN; n += nwarps) {
        int rs = g_rs[n];
        int deg = g_cnt[n];
        float adv = g_ad1[n * 4 + head];

        float a0 = 0.f, a1 = 0.f, a2 = 0.f, a3 = 0.f;
        float a4 = 0.f, a5 = 0.f, a6 = 0.f, a7 = 0.f, den = 0.f;

        for (int j = 0; j < deg; j += 8) {
            int j0 = j + grp, j1 = j + grp + 4;
            int s0 = g_srcs[rs + (j0 < deg ? j0 : deg - 1)];
            int s1 = g_srcs[rs + (j1 < deg ? j1 : deg - 1)];
            float c0 = g_as1[s0 * 4 + head];
            float c1 = g_as1[s1 * 4 + head];
            float4 r0 = h4[s0 * 8 + q];
            float4 r1 = h4[s1 * 8 + q];
            float e0 = (j0 < deg) ? __expf(lrelu(c0 + adv)) : 0.f;
            float e1 = (j1 < deg) ? __expf(lrelu(c1 + adv)) : 0.f;
            den += e0 + e1;
            const __half2* p0 = (const __half2*)&r0;
            const __half2* p1 = (const __half2*)&r1;
            float2 v;
            v = __half22float2(p0[0]); a0 += e0 * v.x; a1 += e0 * v.y;
            v = __half22float2(p0[1]); a2 += e0 * v.x; a3 += e0 * v.y;
            v = __half22float2(p0[2]); a4 += e0 * v.x; a5 += e0 * v.y;
            v = __half22float2(p0[3]); a6 += e0 * v.x; a7 += e0 * v.y;
            v = __half22float2(p1[0]); a0 += e1 * v.x; a1 += e1 * v.y;
            v = __half22float2(p1[1]); a2 += e1 * v.x; a3 += e1 * v.y;
            v = __half22float2(p1[2]); a4 += e1 * v.x; a5 += e1 * v.y;
            v = __half22float2(p1[3]); a6 += e1 * v.x; a7 += e1 * v.y;
        }
#pragma unroll
        for (int off = 8; off <= 16; off <<= 1) {
            den += __shfl_xor_sync(0xffffffffu, den, off);
            a0 += __shfl_xor_sync(0xffffffffu, a0, off);
            a1 += __shfl_xor_sync(0xffffffffu, a1, off);
            a2 += __shfl_xor_sync(0xffffffffu, a2, off);
            a3 += __shfl_xor_sync(0xffffffffu, a3, off);
            a4 += __shfl_xor_sync(0xffffffffu, a4, off);
            a5 += __shfl_xor_sync(0xffffffffu, a5, off);
            a6 += __shfl_xor_sync(0xffffffffu, a6, off);
            a7 += __shfl_xor_sync(0xffffffffu, a7, off);
        }
        float inv = 1.f / (den + 1e-16f);
        if (grp == 0) {
            float4* dst = (float4*)g_agg1 + n * 16 + q * 2;
            float4 o;
            o.x = a0 * inv; o.y = a1 * inv; o.z = a2 * inv; o.w = a3 * inv;
            dst[0] = o;
            o.x = a4 * inv; o.y = a5 * inv; o.z = a6 * inv; o.w = a7 * inv;
            dst[1] = o;
        }
    }
}

// ---------------- layer-2 GEMM (round-11 form) ----------------
__global__ void k_gemm2(const float* __restrict__ W2, const float* __restrict__ b1,
                        const float* __restrict__ a_src, const float* __restrict__ a_dst) {
    __shared__ float2 Wsh[HID * 32];      // 16 KB
    __shared__ float4 Xsh[8][HID];        // 8 KB
    int tid = threadIdx.x;
    for (int i = tid; i < HID * 32; i += 256) Wsh[i] = ((const float2*)W2)[i];

    int lane = tid & 31, w = tid >> 5;
    int r0 = (blockIdx.x * 8 + w) * 4;
    float b0 = __ldg(&b1[2 * lane]), b1v = __ldg(&b1[2 * lane + 1]);

    {
        float4 c0, c1;
        float2 v0 = ((const float2*)g_agg1)[(r0 + 0) * 32 + lane];
        float2 v1 = ((const float2*)g_agg1)[(r0 + 1) * 32 + lane];
        float2 v2 = ((const float2*)g_agg1)[(r0 + 2) * 32 + lane];
        float2 v3 = ((const float2*)g_agg1)[(r0 + 3) * 32 + lane];
        c0.x = fmaxf(v0.x + b0, 0.f);  c1.x = fmaxf(v0.y + b1v, 0.f);
        c0.y = fmaxf(v1.x + b0, 0.f);  c1.y = fmaxf(v1.y + b1v, 0.f);
        c0.z = fmaxf(v2.x + b0, 0.f);  c1.z = fmaxf(v2.y + b1v, 0.f);
        c0.w = fmaxf(v3.x + b0, 0.f);  c1.w = fmaxf(v3.y + b1v, 0.f);
        Xsh[w][2 * lane] = c0;
        Xsh[w][2 * lane + 1] = c1;
    }
    __syncthreads();

    float acc0[4] = {}, acc1[4] = {};
#pragma unroll
    for (int k = 0; k < HID; k++) {
        float4 xv = Xsh[w][k];
        float2 wv = Wsh[k * 32 + lane];
        acc0[0] += xv.x * wv.x;  acc1[0] += xv.x * wv.y;
        acc0[1] += xv.y * wv.x;  acc1[1] += xv.y * wv.y;
        acc0[2] += xv.z * wv.x;  acc1[2] += xv.z * wv.y;
        acc0[3] += xv.w * wv.x;  acc1[3] += xv.w * wv.y;
    }

    float s0 = __ldg(&a_src[2 * lane]), s1 = __ldg(&a_src[2 * lane + 1]);
    float d0 = __ldg(&a_dst[2 * lane]), d1 = __ldg(&a_dst[2 * lane + 1]);

#pragma unroll
    for (int i = 0; i < 4; i++) {
        int row = r0 + i;
        g_h2h[row * 32 + lane] = __floats2half2_rn(acc0[i], acc1[i]);
        float pa = acc0[i] * s0 + acc1[i] * s1;
        float pd = acc0[i] * d0 + acc1[i] * d1;
#pragma unroll
        for (int off = 16; off; off >>= 1) {
            pa += __shfl_xor_sync(0xffffffffu, pa, off);
            pd += __shfl_xor_sync(0xffffffffu, pd, off);
        }
        if (lane == 0) {
            g_as2[row] = pa;
            g_ad2[row] = pd;
        }
    }
}

// ---------------- layer-2 gather aggregation + projection: node-strided warps ----------------
__global__ void k_agg2f(const float* __restrict__ b2, const float* __restrict__ Wc,
                        const float* __restrict__ bc, float* __restrict__ out) {
    int lane = threadIdx.x & 31;
    int grp = lane >> 3;
    int q = lane & 7;
    int wglob = blockIdx.x * 8 + (threadIdx.x >> 5);
    const int nwarps = 1250 * 8;

    const float4* h4 = (const float4*)g_h2h;
    float4 ba = ((const float4*)b2)[q * 2],  bb = ((const float4*)b2)[q * 2 + 1];
    float4 wa = ((const float4*)Wc)[q * 2],  wb = ((const float4*)Wc)[q * 2 + 1];
    float bcv = __ldg(&bc[0]);

    for (int n = wglob; n < NN; n += nwarps) {
        int rs = g_rs[n];
        int deg = g_cnt[n];
        float adv = g_ad2[n];

        float a0 = 0.f, a1 = 0.f, a2 = 0.f, a3 = 0.f;
        float a4 = 0.f, a5 = 0.f, a6 = 0.f, a7 = 0.f, den = 0.f;

        for (int j = 0; j < deg; j += 8) {
            int j0 = j + grp, j1 = j + grp + 4;
            int s0 = g_srcs[rs + (j0 < deg ? j0 : deg - 1)];
            int s1 = g_srcs[rs + (j1 < deg ? j1 : deg - 1)];
            float c0 = g_as2[s0];
            float c1 = g_as2[s1];
            float4 r0 = h4[s0 * 8 + q];
            float4 r1 = h4[s1 * 8 + q];
            float e0 = (j0 < deg) ? __expf(lrelu(c0 + adv)) : 0.f;
            float e1 = (j1 < deg) ? __expf(lrelu(c1 + adv)) : 0.f;
            den += e0 + e1;
            const __half2* p0 = (const __half2*)&r0;
            const __half2* p1 = (const __half2*)&r1;
            float2 v;
            v = __half22float2(p0[0]); a0 += e0 * v.x; a1 += e0 * v.y;
            v = __half22float2(p0[1]); a2 += e0 * v.x; a3 += e0 * v.y;
            v = __half22float2(p0[2]); a4 += e0 * v.x; a5 += e0 * v.y;
            v = __half22float2(p0[3]); a6 += e0 * v.x; a7 += e0 * v.y;
            v = __half22float2(p1[0]); a0 += e1 * v.x; a1 += e1 * v.y;
            v = __half22float2(p1[1]); a2 += e1 * v.x; a3 += e1 * v.y;
            v = __half22float2(p1[2]); a4 += e1 * v.x; a5 += e1 * v.y;
            v = __half22float2(p1[3]); a6 += e1 * v.x; a7 += e1 * v.y;
        }
#pragma unroll
        for (int off = 8; off <= 16; off <<= 1) {
            den += __shfl_xor_sync(0xffffffffu, den, off);
            a0 += __shfl_xor_sync(0xffffffffu, a0, off);
            a1 += __shfl_xor_sync(0xffffffffu, a1, off);
            a2 += __shfl_xor_sync(0xffffffffu, a2, off);
            a3 += __shfl_xor_sync(0xffffffffu, a3, off);
            a4 += __shfl_xor_sync(0xffffffffu, a4, off);
            a5 += __shfl_xor_sync(0xffffffffu, a5, off);
            a6 += __shfl_xor_sync(0xffffffffu, a6, off);
            a7 += __shfl_xor_sync(0xffffffffu, a7, off);
        }
        float inv = 1.f / (den + 1e-16f);
        float v = fmaxf(a0 * inv + ba.x, 0.f) * wa.x
                + fmaxf(a1 * inv + ba.y, 0.f) * wa.y
                + fmaxf(a2 * inv + ba.z, 0.f) * wa.z
                + fmaxf(a3 * inv + ba.w, 0.f) * wa.w
                + fmaxf(a4 * inv + bb.x, 0.f) * wb.x
                + fmaxf(a5 * inv + bb.y, 0.f) * wb.y
                + fmaxf(a6 * inv + bb.z, 0.f) * wb.z
                + fmaxf(a7 * inv + bb.w, 0.f) * wb.w;
#pragma unroll
        for (int off = 1; off <= 4; off <<= 1) v += __shfl_xor_sync(0xffffffffu, v, off);
        if (lane == 0) {
            out[n] = v + bcv;
            g_cnt[n] = 0;  // restore invariant for next call's histogram
        }
    }
}

extern "C" void kernel_launch(void* const* d_in, const int* in_sizes, int n_in,
                              void* d_out, int out_size) {
    const float* x      = (const float*)d_in[0];
    const int* ei       = (const int*)d_in[1];   // JAX x64 disabled -> int32
    const float* W1     = (const float*)d_in[2];
    const float* a_src1 = (const float*)d_in[3];
    const float* a_dst1 = (const float*)d_in[4];
    const float* b1     = (const float*)d_in[5];
    const float* W2     = (const float*)d_in[6];
    const float* a_src2 = (const float*)d_in[7];
    const float* a_dst2 = (const float*)d_in[8];
    const float* b2     = (const float*)d_in[9];
    const float* Wc     = (const float*)d_in[10];
    const float* bc     = (const float*)d_in[11];
    float* out          = (float*)d_out;
    (void)in_sizes; (void)n_in; (void)out_size;

    k_gemm1h<<<3125, 256>>>(x, W1, a_src1, a_dst1, ei);  // 1: GEMM1 + degree hist
    k_alloc<<<(NN + 255) / 256, 256>>>();                // 2: CSR range alloc
    k_fill<<<(EE + 255) / 256, 256>>>(ei);               // 3: CSR fill
    k_agg1<<<1250, 256>>>();                             // 4: <- ncu sample
    k_gemm2<<<3125, 256>>>(W2, b1, a_src2, a_dst2);      // 5
    k_agg2f<<<1250, 256>>>(b2, Wc, bc, out);             // 6
}

// round 14
// speedup vs baseline: 1.0186x; 1.0172x over previous
#include <cuda_runtime.h>
#include <cuda_fp16.h>

#define NN 100000
#define EE 1600000
#define FIN 128
#define HID 64

// ---- scratch (static __device__ — no allocation) ----
__device__ __align__(16) __half2 g_h1h[NN * 32];  // h1, fp16, feature pairs (128B/row)
__device__ __align__(16) __half2 g_h2h[NN * 32];  // h2, fp16
__device__ __align__(16) float g_as1[NN * 4];
__device__ __align__(16) float g_ad1[NN * 4];
__device__ __align__(16) float g_agg1[NN * HID];
__device__ __align__(16) float g_as2[NN];
__device__ __align__(16) float g_ad2[NN];
__device__ int g_cnt[NN];    // degree by dst (zero at load; re-zeroed by agg2f each call)
__device__ int g_rs[NN];     // CSR row starts (unordered ranges)
__device__ int g_cur[NN];    // fill cursors
__device__ int g_srcs[EE];   // CSR: src per incident edge, grouped by dst
__device__ int g_total;      // range-allocation cursor (reset by k_fill each call)

__device__ __forceinline__ float lrelu(float t) { return fmaxf(t, 0.2f * t); }

// ---------------- layer-1 GEMM (+ fused degree histogram) ----------------
__global__ void k_gemm1h(const float* __restrict__ x, const float* __restrict__ W1,
                         const float* __restrict__ a_src, const float* __restrict__ a_dst,
                         const int* __restrict__ ei) {
    __shared__ float2 Wsh[FIN * 32];      // 32 KB
    __shared__ float4 Xsh[8][FIN];        // 16 KB
    int tid = threadIdx.x;

    // fused histogram: exactly 2 edges per thread (3125*512 == EE)
    {
        int e = blockIdx.x * 512 + tid;
        atomicAdd(&g_cnt[__ldg(&ei[EE + e])], 1);
        atomicAdd(&g_cnt[__ldg(&ei[EE + e + 256])], 1);
    }

    for (int i = tid; i < FIN * 32; i += 256) Wsh[i] = ((const float2*)W1)[i];

    int lane = tid & 31, w = tid >> 5;
    int r0 = (blockIdx.x * 8 + w) * 4;

#pragma unroll
    for (int j = 0; j < 4; j++) {
        float4 v;
        v.x = x[(r0 + 0) * FIN + 32 * j + lane];
        v.y = x[(r0 + 1) * FIN + 32 * j + lane];
        v.z = x[(r0 + 2) * FIN + 32 * j + lane];
        v.w = x[(r0 + 3) * FIN + 32 * j + lane];
        Xsh[w][32 * j + lane] = v;
    }
    __syncthreads();

    float acc0[4] = {}, acc1[4] = {};
#pragma unroll
    for (int k = 0; k < FIN; k++) {
        float4 xv = Xsh[w][k];            // LDS.128 broadcast
        float2 wv = Wsh[k * 32 + lane];   // LDS.64
        acc0[0] += xv.x * wv.x;  acc1[0] += xv.x * wv.y;
        acc0[1] += xv.y * wv.x;  acc1[1] += xv.y * wv.y;
        acc0[2] += xv.z * wv.x;  acc1[2] += xv.z * wv.y;
        acc0[3] += xv.w * wv.x;  acc1[3] += xv.w * wv.y;
    }

    float s0 = __ldg(&a_src[2 * lane]), s1 = __ldg(&a_src[2 * lane + 1]);
    float d0 = __ldg(&a_dst[2 * lane]), d1 = __ldg(&a_dst[2 * lane + 1]);

#pragma unroll
    for (int i = 0; i < 4; i++) {
        int row = r0 + i;
        g_h1h[row * 32 + lane] = __floats2half2_rn(acc0[i], acc1[i]);
        float pa = acc0[i] * s0 + acc1[i] * s1;
        float pd = acc0[i] * d0 + acc1[i] * d1;
#pragma unroll
        for (int off = 4; off; off >>= 1) {
            pa += __shfl_xor_sync(0xffffffffu, pa, off);
            pd += __shfl_xor_sync(0xffffffffu, pd, off);
        }
        if ((lane & 7) == 0) {
            g_as1[row * 4 + (lane >> 3)] = pa;
            g_ad1[row * 4 + (lane >> 3)] = pd;
        }
    }
}

// ---------------- CSR range allocation ----------------
__global__ void k_alloc() {
    int i = blockIdx.x * blockDim.x + threadIdx.x;
    int lane = threadIdx.x & 31;
    int c = (i < NN) ? g_cnt[i] : 0;
    int s = c;
#pragma unroll
    for (int off = 1; off < 32; off <<= 1) {
        int t = __shfl_up_sync(0xffffffffu, s, off);
        if (lane >= off) s += t;
    }
    int wtot = __shfl_sync(0xffffffffu, s, 31);
    int base = 0;
    if (lane == 31) base = atomicAdd(&g_total, wtot);
    base = __shfl_sync(0xffffffffu, base, 31);
    if (i < NN) {
        int r = base + s - c;
        g_rs[i] = r;
        g_cur[i] = r;
    }
}

__global__ void k_fill(const int* __restrict__ ei) {
    int e = blockIdx.x * blockDim.x + threadIdx.x;
    if (e == 0) g_total = 0;
    if (e < EE) {
        int s = __ldg(&ei[e]);
        int d = __ldg(&ei[EE + e]);
        int p = atomicAdd(&g_cur[d], 1);
        g_srcs[p] = s;
    }
}

// ---------------- layer-1 gather aggregation: node-strided warps (round-13 form) ----------------
__global__ void k_agg1() {
    int lane = threadIdx.x & 31;
    int grp = lane >> 3;
    int q = lane & 7;
    int head = q >> 1;
    int wglob = blockIdx.x * 8 + (threadIdx.x >> 5);
    const int nwarps = 1250 * 8;

    const float4* h4 = (const float4*)g_h1h;

    for (int n = wglob; n < NN; n += nwarps) {
        int rs = g_rs[n];
        int deg = g_cnt[n];
        float adv = g_ad1[n * 4 + head];

        float a0 = 0.f, a1 = 0.f, a2 = 0.f, a3 = 0.f;
        float a4 = 0.f, a5 = 0.f, a6 = 0.f, a7 = 0.f, den = 0.f;

        for (int j = 0; j < deg; j += 8) {
            int j0 = j + grp, j1 = j + grp + 4;
            int s0 = g_srcs[rs + (j0 < deg ? j0 : deg - 1)];
            int s1 = g_srcs[rs + (j1 < deg ? j1 : deg - 1)];
            float c0 = g_as1[s0 * 4 + head];
            float c1 = g_as1[s1 * 4 + head];
            float4 r0 = h4[s0 * 8 + q];
            float4 r1 = h4[s1 * 8 + q];
            float e0 = (j0 < deg) ? __expf(lrelu(c0 + adv)) : 0.f;
            float e1 = (j1 < deg) ? __expf(lrelu(c1 + adv)) : 0.f;
            den += e0 + e1;
            const __half2* p0 = (const __half2*)&r0;
            const __half2* p1 = (const __half2*)&r1;
            float2 v;
            v = __half22float2(p0[0]); a0 += e0 * v.x; a1 += e0 * v.y;
            v = __half22float2(p0[1]); a2 += e0 * v.x; a3 += e0 * v.y;
            v = __half22float2(p0[2]); a4 += e0 * v.x; a5 += e0 * v.y;
            v = __half22float2(p0[3]); a6 += e0 * v.x; a7 += e0 * v.y;
            v = __half22float2(p1[0]); a0 += e1 * v.x; a1 += e1 * v.y;
            v = __half22float2(p1[1]); a2 += e1 * v.x; a3 += e1 * v.y;
            v = __half22float2(p1[2]); a4 += e1 * v.x; a5 += e1 * v.y;
            v = __half22float2(p1[3]); a6 += e1 * v.x; a7 += e1 * v.y;
        }
#pragma unroll
        for (int off = 8; off <= 16; off <<= 1) {
            den += __shfl_xor_sync(0xffffffffu, den, off);
            a0 += __shfl_xor_sync(0xffffffffu, a0, off);
            a1 += __shfl_xor_sync(0xffffffffu, a1, off);
            a2 += __shfl_xor_sync(0xffffffffu, a2, off);
            a3 += __shfl_xor_sync(0xffffffffu, a3, off);
            a4 += __shfl_xor_sync(0xffffffffu, a4, off);
            a5 += __shfl_xor_sync(0xffffffffu, a5, off);
            a6 += __shfl_xor_sync(0xffffffffu, a6, off);
            a7 += __shfl_xor_sync(0xffffffffu, a7, off);
        }
        float inv = 1.f / (den + 1e-16f);
        if (grp == 0) {
            float4* dst = (float4*)g_agg1 + n * 16 + q * 2;
            float4 o;
            o.x = a0 * inv; o.y = a1 * inv; o.z = a2 * inv; o.w = a3 * inv;
            dst[0] = o;
            o.x = a4 * inv; o.y = a5 * inv; o.z = a6 * inv; o.w = a7 * inv;
            dst[1] = o;
        }
    }
}

// ---------------- layer-2 GEMM (round-11 form) ----------------
__global__ void k_gemm2(const float* __restrict__ W2, const float* __restrict__ b1,
                        const float* __restrict__ a_src, const float* __restrict__ a_dst) {
    __shared__ float2 Wsh[HID * 32];      // 16 KB
    __shared__ float4 Xsh[8][HID];        // 8 KB
    int tid = threadIdx.x;
    for (int i = tid; i < HID * 32; i += 256) Wsh[i] = ((const float2*)W2)[i];

    int lane = tid & 31, w = tid >> 5;
    int r0 = (blockIdx.x * 8 + w) * 4;
    float b0 = __ldg(&b1[2 * lane]), b1v = __ldg(&b1[2 * lane + 1]);

    {
        float4 c0, c1;
        float2 v0 = ((const float2*)g_agg1)[(r0 + 0) * 32 + lane];
        float2 v1 = ((const float2*)g_agg1)[(r0 + 1) * 32 + lane];
        float2 v2 = ((const float2*)g_agg1)[(r0 + 2) * 32 + lane];
        float2 v3 = ((const float2*)g_agg1)[(r0 + 3) * 32 + lane];
        c0.x = fmaxf(v0.x + b0, 0.f);  c1.x = fmaxf(v0.y + b1v, 0.f);
        c0.y = fmaxf(v1.x + b0, 0.f);  c1.y = fmaxf(v1.y + b1v, 0.f);
        c0.z = fmaxf(v2.x + b0, 0.f);  c1.z = fmaxf(v2.y + b1v, 0.f);
        c0.w = fmaxf(v3.x + b0, 0.f);  c1.w = fmaxf(v3.y + b1v, 0.f);
        Xsh[w][2 * lane] = c0;
        Xsh[w][2 * lane + 1] = c1;
    }
    __syncthreads();

    float acc0[4] = {}, acc1[4] = {};
#pragma unroll
    for (int k = 0; k < HID; k++) {
        float4 xv = Xsh[w][k];
        float2 wv = Wsh[k * 32 + lane];
        acc0[0] += xv.x * wv.x;  acc1[0] += xv.x * wv.y;
        acc0[1] += xv.y * wv.x;  acc1[1] += xv.y * wv.y;
        acc0[2] += xv.z * wv.x;  acc1[2] += xv.z * wv.y;
        acc0[3] += xv.w * wv.x;  acc1[3] += xv.w * wv.y;
    }

    float s0 = __ldg(&a_src[2 * lane]), s1 = __ldg(&a_src[2 * lane + 1]);
    float d0 = __ldg(&a_dst[2 * lane]), d1 = __ldg(&a_dst[2 * lane + 1]);

#pragma unroll
    for (int i = 0; i < 4; i++) {
        int row = r0 + i;
        g_h2h[row * 32 + lane] = __floats2half2_rn(acc0[i], acc1[i]);
        float pa = acc0[i] * s0 + acc1[i] * s1;
        float pd = acc0[i] * d0 + acc1[i] * d1;
#pragma unroll
        for (int off = 16; off; off >>= 1) {
            pa += __shfl_xor_sync(0xffffffffu, pa, off);
            pd += __shfl_xor_sync(0xffffffffu, pd, off);
        }
        if (lane == 0) {
            g_as2[row] = pa;
            g_ad2[row] = pd;
        }
    }
}

// ---------------- layer-2 gather aggregation + projection (round-11 block-per-node form) ----------------
__global__ void k_agg2f(const float* __restrict__ b2, const float* __restrict__ Wc,
                        const float* __restrict__ bc, float* __restrict__ out) {
    int n = blockIdx.x * 8 + (threadIdx.x >> 5);
    if (n >= NN) return;
    int lane = threadIdx.x & 31;
    int grp = lane >> 3;
    int q = lane & 7;

    int rs = g_rs[n];
    int deg = g_cnt[n];
    float adv = g_ad2[n];

    float a0 = 0.f, a1 = 0.f, a2 = 0.f, a3 = 0.f;
    float a4 = 0.f, a5 = 0.f, a6 = 0.f, a7 = 0.f, den = 0.f;

    const float4* h4 = (const float4*)g_h2h;
    for (int j = 0; j < deg; j += 8) {
        int j0 = j + grp, j1 = j + grp + 4;
        int s0 = g_srcs[rs + (j0 < deg ? j0 : deg - 1)];
        int s1 = g_srcs[rs + (j1 < deg ? j1 : deg - 1)];
        float c0 = g_as2[s0];
        float c1 = g_as2[s1];
        float4 r0 = h4[s0 * 8 + q];
        float4 r1 = h4[s1 * 8 + q];
        float e0 = (j0 < deg) ? __expf(lrelu(c0 + adv)) : 0.f;
        float e1 = (j1 < deg) ? __expf(lrelu(c1 + adv)) : 0.f;
        den += e0 + e1;
        const __half2* p0 = (const __half2*)&r0;
        const __half2* p1 = (const __half2*)&r1;
        float2 v;
        v = __half22float2(p0[0]); a0 += e0 * v.x; a1 += e0 * v.y;
        v = __half22float2(p0[1]); a2 += e0 * v.x; a3 += e0 * v.y;
        v = __half22float2(p0[2]); a4 += e0 * v.x; a5 += e0 * v.y;
        v = __half22float2(p0[3]); a6 += e0 * v.x; a7 += e0 * v.y;
        v = __half22float2(p1[0]); a0 += e1 * v.x; a1 += e1 * v.y;
        v = __half22float2(p1[1]); a2 += e1 * v.x; a3 += e1 * v.y;
        v = __half22float2(p1[2]); a4 += e1 * v.x; a5 += e1 * v.y;
        v = __half22float2(p1[3]); a6 += e1 * v.x; a7 += e1 * v.y;
    }
#pragma unroll
    for (int off = 8; off <= 16; off <<= 1) {
        den += __shfl_xor_sync(0xffffffffu, den, off);
        a0 += __shfl_xor_sync(0xffffffffu, a0, off);
        a1 += __shfl_xor_sync(0xffffffffu, a1, off);
        a2 += __shfl_xor_sync(0xffffffffu, a2, off);
        a3 += __shfl_xor_sync(0xffffffffu, a3, off);
        a4 += __shfl_xor_sync(0xffffffffu, a4, off);
        a5 += __shfl_xor_sync(0xffffffffu, a5, off);
        a6 += __shfl_xor_sync(0xffffffffu, a6, off);
        a7 += __shfl_xor_sync(0xffffffffu, a7, off);
    }
    float inv = 1.f / (den + 1e-16f);
    float4 ba = ((const float4*)b2)[q * 2],  bb = ((const float4*)b2)[q * 2 + 1];
    float4 wa = ((const float4*)Wc)[q * 2],  wb = ((const float4*)Wc)[q * 2 + 1];
    float v = fmaxf(a0 * inv + ba.x, 0.f) * wa.x
            + fmaxf(a1 * inv + ba.y, 0.f) * wa.y
            + fmaxf(a2 * inv + ba.z, 0.f) * wa.z
            + fmaxf(a3 * inv + ba.w, 0.f) * wa.w
            + fmaxf(a4 * inv + bb.x, 0.f) * wb.x
            + fmaxf(a5 * inv + bb.y, 0.f) * wb.y
            + fmaxf(a6 * inv + bb.z, 0.f) * wb.z
            + fmaxf(a7 * inv + bb.w, 0.f) * wb.w;
#pragma unroll
    for (int off = 1; off <= 4; off <<= 1) v += __shfl_xor_sync(0xffffffffu, v, off);
    if (lane == 0) {
        out[n] = v + __ldg(&bc[0]);
        g_cnt[n] = 0;  // restore invariant for next call's histogram
    }
}

extern "C" void kernel_launch(void* const* d_in, const int* in_sizes, int n_in,
                              void* d_out, int out_size) {
    const float* x      = (const float*)d_in[0];
    const int* ei       = (const int*)d_in[1];   // JAX x64 disabled -> int32
    const float* W1     = (const float*)d_in[2];
    const float* a_src1 = (const float*)d_in[3];
    const float* a_dst1 = (const float*)d_in[4];
    const float* b1     = (const float*)d_in[5];
    const float* W2     = (const float*)d_in[6];
    const float* a_src2 = (const float*)d_in[7];
    const float* a_dst2 = (const float*)d_in[8];
    const float* b2     = (const float*)d_in[9];
    const float* Wc     = (const float*)d_in[10];
    const float* bc     = (const float*)d_in[11];
    float* out          = (float*)d_out;
    (void)in_sizes; (void)n_in; (void)out_size;

    k_gemm1h<<<3125, 256>>>(x, W1, a_src1, a_dst1, ei);  // 1: GEMM1 + degree hist
    k_alloc<<<(NN + 255) / 256, 256>>>();                // 2: CSR range alloc
    k_fill<<<(EE + 255) / 256, 256>>>(ei);               // 3: CSR fill
    k_agg1<<<1250, 256>>>();                             // 4: <- ncu sample
    k_gemm2<<<3125, 256>>>(W2, b1, a_src2, a_dst2);      // 5
    k_agg2f<<<12500, 256>>>(b2, Wc, bc, out);            // 6
}

// round 15
// speedup vs baseline: 1.0198x; 1.0012x over previous
#include <cuda_runtime.h>
#include <cuda_fp16.h>

#define NN 100000
#define EE 1600000
#define FIN 128
#define HID 64

// ---- scratch (static __device__ — no allocation) ----
__device__ __align__(16) __half2 g_h1h[NN * 32];  // h1, fp16, feature pairs (128B/row)
__device__ __align__(16) __half2 g_h2h[NN * 32];  // h2, fp16
__device__ __align__(16) float g_as1[NN * 4];
__device__ __align__(16) float g_ad1[NN * 4];
__device__ __align__(16) float g_agg1[NN * HID];
__device__ __align__(16) float g_as2[NN];
__device__ __align__(16) float g_ad2[NN];
__device__ int g_cnt[NN];    // degree by dst (zero at load; re-zeroed by agg2f each call)
__device__ int g_rs[NN];     // CSR row starts (unordered ranges)
__device__ int g_cur[NN];    // fill cursors
__device__ int g_srcs[EE];   // CSR: src per incident edge, grouped by dst
__device__ int g_total;      // range-allocation cursor (reset by k_fill each call)

__device__ __forceinline__ float lrelu(float t) { return fmaxf(t, 0.2f * t); }

// forced (non-hoistable) 16B global load
__device__ __forceinline__ float4 ldg128_volatile(const float* p) {
    float4 r;
    asm volatile("ld.global.nc.v4.f32 {%0,%1,%2,%3}, [%4];"
                 : "=f"(r.x), "=f"(r.y), "=f"(r.z), "=f"(r.w) : "l"(p));
    return r;
}

// ---------------- layer-1 GEMM (+ fused degree histogram) ----------------
__global__ void k_gemm1h(const float* __restrict__ x, const float* __restrict__ W1,
                         const float* __restrict__ a_src, const float* __restrict__ a_dst,
                         const int* __restrict__ ei) {
    __shared__ float2 Wsh[FIN * 32];      // 32 KB
    __shared__ float4 Xsh[8][FIN];        // 16 KB
    int tid = threadIdx.x;

    // fused histogram: exactly 2 edges per thread (3125*512 == EE)
    {
        int e = blockIdx.x * 512 + tid;
        atomicAdd(&g_cnt[__ldg(&ei[EE + e])], 1);
        atomicAdd(&g_cnt[__ldg(&ei[EE + e + 256])], 1);
    }

    for (int i = tid; i < FIN * 32; i += 256) Wsh[i] = ((const float2*)W1)[i];

    int lane = tid & 31, w = tid >> 5;
    int r0 = (blockIdx.x * 8 + w) * 4;

#pragma unroll
    for (int j = 0; j < 4; j++) {
        float4 v;
        v.x = x[(r0 + 0) * FIN + 32 * j + lane];
        v.y = x[(r0 + 1) * FIN + 32 * j + lane];
        v.z = x[(r0 + 2) * FIN + 32 * j + lane];
        v.w = x[(r0 + 3) * FIN + 32 * j + lane];
        Xsh[w][32 * j + lane] = v;
    }
    __syncthreads();

    float acc0[4] = {}, acc1[4] = {};
#pragma unroll
    for (int k = 0; k < FIN; k++) {
        float4 xv = Xsh[w][k];            // LDS.128 broadcast
        float2 wv = Wsh[k * 32 + lane];   // LDS.64
        acc0[0] += xv.x * wv.x;  acc1[0] += xv.x * wv.y;
        acc0[1] += xv.y * wv.x;  acc1[1] += xv.y * wv.y;
        acc0[2] += xv.z * wv.x;  acc1[2] += xv.z * wv.y;
        acc0[3] += xv.w * wv.x;  acc1[3] += xv.w * wv.y;
    }

    float s0 = __ldg(&a_src[2 * lane]), s1 = __ldg(&a_src[2 * lane + 1]);
    float d0 = __ldg(&a_dst[2 * lane]), d1 = __ldg(&a_dst[2 * lane + 1]);

#pragma unroll
    for (int i = 0; i < 4; i++) {
        int row = r0 + i;
        g_h1h[row * 32 + lane] = __floats2half2_rn(acc0[i], acc1[i]);
        float pa = acc0[i] * s0 + acc1[i] * s1;
        float pd = acc0[i] * d0 + acc1[i] * d1;
#pragma unroll
        for (int off = 4; off; off >>= 1) {
            pa += __shfl_xor_sync(0xffffffffu, pa, off);
            pd += __shfl_xor_sync(0xffffffffu, pd, off);
        }
        if ((lane & 7) == 0) {
            g_as1[row * 4 + (lane >> 3)] = pa;
            g_ad1[row * 4 + (lane >> 3)] = pd;
        }
    }
}

// ---------------- CSR range allocation ----------------
__global__ void k_alloc() {
    int i = blockIdx.x * blockDim.x + threadIdx.x;
    int lane = threadIdx.x & 31;
    int c = (i < NN) ? g_cnt[i] : 0;
    int s = c;
#pragma unroll
    for (int off = 1; off < 32; off <<= 1) {
        int t = __shfl_up_sync(0xffffffffu, s, off);
        if (lane >= off) s += t;
    }
    int wtot = __shfl_sync(0xffffffffu, s, 31);
    int base = 0;
    if (lane == 31) base = atomicAdd(&g_total, wtot);
    base = __shfl_sync(0xffffffffu, base, 31);
    if (i < NN) {
        int r = base + s - c;
        g_rs[i] = r;
        g_cur[i] = r;
    }
}

__global__ void k_fill(const int* __restrict__ ei) {
    int e = blockIdx.x * blockDim.x + threadIdx.x;
    if (e == 0) g_total = 0;
    if (e < EE) {
        int s = __ldg(&ei[e]);
        int d = __ldg(&ei[EE + e]);
        int p = atomicAdd(&g_cur[d], 1);
        g_srcs[p] = s;
    }
}

// ---------------- layer-1 gather aggregation: node-strided warps ----------------
__global__ void k_agg1() {
    int lane = threadIdx.x & 31;
    int grp = lane >> 3;
    int q = lane & 7;
    int head = q >> 1;
    int wglob = blockIdx.x * 8 + (threadIdx.x >> 5);
    const int nwarps = 1250 * 8;

    const float4* h4 = (const float4*)g_h1h;

    for (int n = wglob; n < NN; n += nwarps) {
        int rs = g_rs[n];
        int deg = g_cnt[n];
        float adv = g_ad1[n * 4 + head];

        float a0 = 0.f, a1 = 0.f, a2 = 0.f, a3 = 0.f;
        float a4 = 0.f, a5 = 0.f, a6 = 0.f, a7 = 0.f, den = 0.f;

        for (int j = 0; j < deg; j += 8) {
            int j0 = j + grp, j1 = j + grp + 4;
            int s0 = g_srcs[rs + (j0 < deg ? j0 : deg - 1)];
            int s1 = g_srcs[rs + (j1 < deg ? j1 : deg - 1)];
            float c0 = g_as1[s0 * 4 + head];
            float c1 = g_as1[s1 * 4 + head];
            float4 r0 = h4[s0 * 8 + q];
            float4 r1 = h4[s1 * 8 + q];
            float e0 = (j0 < deg) ? __expf(lrelu(c0 + adv)) : 0.f;
            float e1 = (j1 < deg) ? __expf(lrelu(c1 + adv)) : 0.f;
            den += e0 + e1;
            const __half2* p0 = (const __half2*)&r0;
            const __half2* p1 = (const __half2*)&r1;
            float2 v;
            v = __half22float2(p0[0]); a0 += e0 * v.x; a1 += e0 * v.y;
            v = __half22float2(p0[1]); a2 += e0 * v.x; a3 += e0 * v.y;
            v = __half22float2(p0[2]); a4 += e0 * v.x; a5 += e0 * v.y;
            v = __half22float2(p0[3]); a6 += e0 * v.x; a7 += e0 * v.y;
            v = __half22float2(p1[0]); a0 += e1 * v.x; a1 += e1 * v.y;
            v = __half22float2(p1[1]); a2 += e1 * v.x; a3 += e1 * v.y;
            v = __half22float2(p1[2]); a4 += e1 * v.x; a5 += e1 * v.y;
            v = __half22float2(p1[3]); a6 += e1 * v.x; a7 += e1 * v.y;
        }
#pragma unroll
        for (int off = 8; off <= 16; off <<= 1) {
            den += __shfl_xor_sync(0xffffffffu, den, off);
            a0 += __shfl_xor_sync(0xffffffffu, a0, off);
            a1 += __shfl_xor_sync(0xffffffffu, a1, off);
            a2 += __shfl_xor_sync(0xffffffffu, a2, off);
            a3 += __shfl_xor_sync(0xffffffffu, a3, off);
            a4 += __shfl_xor_sync(0xffffffffu, a4, off);
            a5 += __shfl_xor_sync(0xffffffffu, a5, off);
            a6 += __shfl_xor_sync(0xffffffffu, a6, off);
            a7 += __shfl_xor_sync(0xffffffffu, a7, off);
        }
        float inv = 1.f / (den + 1e-16f);
        if (grp == 0) {
            float4* dst = (float4*)g_agg1 + n * 16 + q * 2;
            float4 o;
            o.x = a0 * inv; o.y = a1 * inv; o.z = a2 * inv; o.w = a3 * inv;
            dst[0] = o;
            o.x = a4 * inv; o.y = a5 * inv; o.z = a6 * inv; o.w = a7 * inv;
            dst[1] = o;
        }
    }
}

// ---------------- layer-2 GEMM ----------------
__global__ void k_gemm2(const float* __restrict__ W2, const float* __restrict__ b1,
                        const float* __restrict__ a_src, const float* __restrict__ a_dst) {
    __shared__ float2 Wsh[HID * 32];      // 16 KB
    __shared__ float4 Xsh[8][HID];        // 8 KB
    int tid = threadIdx.x;
    for (int i = tid; i < HID * 32; i += 256) Wsh[i] = ((const float2*)W2)[i];

    int lane = tid & 31, w = tid >> 5;
    int r0 = (blockIdx.x * 8 + w) * 4;
    float b0 = __ldg(&b1[2 * lane]), b1v = __ldg(&b1[2 * lane + 1]);

    {
        float4 c0, c1;
        float2 v0 = ((const float2*)g_agg1)[(r0 + 0) * 32 + lane];
        float2 v1 = ((const float2*)g_agg1)[(r0 + 1) * 32 + lane];
        float2 v2 = ((const float2*)g_agg1)[(r0 + 2) * 32 + lane];
        float2 v3 = ((const float2*)g_agg1)[(r0 + 3) * 32 + lane];
        c0.x = fmaxf(v0.x + b0, 0.f);  c1.x = fmaxf(v0.y + b1v, 0.f);
        c0.y = fmaxf(v1.x + b0, 0.f);  c1.y = fmaxf(v1.y + b1v, 0.f);
        c0.z = fmaxf(v2.x + b0, 0.f);  c1.z = fmaxf(v2.y + b1v, 0.f);
        c0.w = fmaxf(v3.x + b0, 0.f);  c1.w = fmaxf(v3.y + b1v, 0.f);
        Xsh[w][2 * lane] = c0;
        Xsh[w][2 * lane + 1] = c1;
    }
    __syncthreads();

    float acc0[4] = {}, acc1[4] = {};
#pragma unroll
    for (int k = 0; k < HID; k++) {
        float4 xv = Xsh[w][k];
        float2 wv = Wsh[k * 32 + lane];
        acc0[0] += xv.x * wv.x;  acc1[0] += xv.x * wv.y;
        acc0[1] += xv.y * wv.x;  acc1[1] += xv.y * wv.y;
        acc0[2] += xv.z * wv.x;  acc1[2] += xv.z * wv.y;
        acc0[3] += xv.w * wv.x;  acc1[3] += xv.w * wv.y;
    }

    float s0 = __ldg(&a_src[2 * lane]), s1 = __ldg(&a_src[2 * lane + 1]);
    float d0 = __ldg(&a_dst[2 * lane]), d1 = __ldg(&a_dst[2 * lane + 1]);

#pragma unroll
    for (int i = 0; i < 4; i++) {
        int row = r0 + i;
        g_h2h[row * 32 + lane] = __floats2half2_rn(acc0[i], acc1[i]);
        float pa = acc0[i] * s0 + acc1[i] * s1;
        float pd = acc0[i] * d0 + acc1[i] * d1;
#pragma unroll
        for (int off = 16; off; off >>= 1) {
            pa += __shfl_xor_sync(0xffffffffu, pa, off);
            pd += __shfl_xor_sync(0xffffffffu, pd, off);
        }
        if (lane == 0) {
            g_as2[row] = pa;
            g_ad2[row] = pd;
        }
    }
}

// ---------------- layer-2 gather aggregation + projection: node-strided warps ----------------
// Projection constants reloaded per node via asm volatile -> not live across the loop.
__global__ void k_agg2f(const float* __restrict__ b2, const float* __restrict__ Wc,
                        const float* __restrict__ bc, float* __restrict__ out) {
    int lane = threadIdx.x & 31;
    int grp = lane >> 3;
    int q = lane & 7;
    int wglob = blockIdx.x * 8 + (threadIdx.x >> 5);
    const int nwarps = 1250 * 8;

    const float4* h4 = (const float4*)g_h2h;

    for (int n = wglob; n < NN; n += nwarps) {
        int rs = g_rs[n];
        int deg = g_cnt[n];
        float adv = g_ad2[n];

        float a0 = 0.f, a1 = 0.f, a2 = 0.f, a3 = 0.f;
        float a4 = 0.f, a5 = 0.f, a6 = 0.f, a7 = 0.f, den = 0.f;

        for (int j = 0; j < deg; j += 8) {
            int j0 = j + grp, j1 = j + grp + 4;
            int s0 = g_srcs[rs + (j0 < deg ? j0 : deg - 1)];
            int s1 = g_srcs[rs + (j1 < deg ? j1 : deg - 1)];
            float c0 = g_as2[s0];
            float c1 = g_as2[s1];
            float4 r0 = h4[s0 * 8 + q];
            float4 r1 = h4[s1 * 8 + q];
            float e0 = (j0 < deg) ? __expf(lrelu(c0 + adv)) : 0.f;
            float e1 = (j1 < deg) ? __expf(lrelu(c1 + adv)) : 0.f;
            den += e0 + e1;
            const __half2* p0 = (const __half2*)&r0;
            const __half2* p1 = (const __half2*)&r1;
            float2 v;
            v = __half22float2(p0[0]); a0 += e0 * v.x; a1 += e0 * v.y;
            v = __half22float2(p0[1]); a2 += e0 * v.x; a3 += e0 * v.y;
            v = __half22float2(p0[2]); a4 += e0 * v.x; a5 += e0 * v.y;
            v = __half22float2(p0[3]); a6 += e0 * v.x; a7 += e0 * v.y;
            v = __half22float2(p1[0]); a0 += e1 * v.x; a1 += e1 * v.y;
            v = __half22float2(p1[1]); a2 += e1 * v.x; a3 += e1 * v.y;
            v = __half22float2(p1[2]); a4 += e1 * v.x; a5 += e1 * v.y;
            v = __half22float2(p1[3]); a6 += e1 * v.x; a7 += e1 * v.y;
        }
#pragma unroll
        for (int off = 8; off <= 16; off <<= 1) {
            den += __shfl_xor_sync(0xffffffffu, den, off);
            a0 += __shfl_xor_sync(0xffffffffu, a0, off);
            a1 += __shfl_xor_sync(0xffffffffu, a1, off);
            a2 += __shfl_xor_sync(0xffffffffu, a2, off);
            a3 += __shfl_xor_sync(0xffffffffu, a3, off);
            a4 += __shfl_xor_sync(0xffffffffu, a4, off);
            a5 += __shfl_xor_sync(0xffffffffu, a5, off);
            a6 += __shfl_xor_sync(0xffffffffu, a6, off);
            a7 += __shfl_xor_sync(0xffffffffu, a7, off);
        }
        float inv = 1.f / (den + 1e-16f);
        // constants reloaded HERE each node (volatile): zero live range in edge loop
        float4 ba = ldg128_volatile(b2 + q * 8);
        float4 bb = ldg128_volatile(b2 + q * 8 + 4);
        float4 wa = ldg128_volatile(Wc + q * 8);
        float4 wb = ldg128_volatile(Wc + q * 8 + 4);
        float v = fmaxf(a0 * inv + ba.x, 0.f) * wa.x
                + fmaxf(a1 * inv + ba.y, 0.f) * wa.y
                + fmaxf(a2 * inv + ba.z, 0.f) * wa.z
                + fmaxf(a3 * inv + ba.w, 0.f) * wa.w
                + fmaxf(a4 * inv + bb.x, 0.f) * wb.x
                + fmaxf(a5 * inv + bb.y, 0.f) * wb.y
                + fmaxf(a6 * inv + bb.z, 0.f) * wb.z
                + fmaxf(a7 * inv + bb.w, 0.f) * wb.w;
#pragma unroll
        for (int off = 1; off <= 4; off <<= 1) v += __shfl_xor_sync(0xffffffffu, v, off);
        if (lane == 0) {
            out[n] = v + __ldg(&bc[0]);
            g_cnt[n] = 0;  // restore invariant for next call's histogram
        }
    }
}

extern "C" void kernel_launch(void* const* d_in, const int* in_sizes, int n_in,
                              void* d_out, int out_size) {
    const float* x      = (const float*)d_in[0];
    const int* ei       = (const int*)d_in[1];   // JAX x64 disabled -> int32
    const float* W1     = (const float*)d_in[2];
    const float* a_src1 = (const float*)d_in[3];
    const float* a_dst1 = (const float*)d_in[4];
    const float* b1     = (const float*)d_in[5];
    const float* W2     = (const float*)d_in[6];
    const float* a_src2 = (const float*)d_in[7];
    const float* a_dst2 = (const float*)d_in[8];
    const float* b2     = (const float*)d_in[9];
    const float* Wc     = (const float*)d_in[10];
    const float* bc     = (const float*)d_in[11];
    float* out          = (float*)d_out;
    (void)in_sizes; (void)n_in; (void)out_size;

    k_gemm1h<<<3125, 256>>>(x, W1, a_src1, a_dst1, ei);  // 1: GEMM1 + degree hist
    k_alloc<<<(NN + 255) / 256, 256>>>();                // 2: CSR range alloc
    k_fill<<<(EE + 255) / 256, 256>>>(ei);               // 3: CSR fill
    k_agg1<<<1250, 256>>>();                             // 4: <- ncu sample
    k_gemm2<<<3125, 256>>>(W2, b1, a_src2, a_dst2);      // 5
    k_agg2f<<<1250, 256>>>(b2, Wc, bc, out);             // 6
}

// round 16
// speedup vs baseline: 1.0413x; 1.0211x over previous
#include <cuda_runtime.h>
#include <cuda_fp16.h>

#define NN 100000
#define EE 1600000
#define FIN 128
#define HID 64

// ---- scratch (static __device__ — no allocation) ----
__device__ __align__(16) __half2 g_h1h[NN * 32];  // h1, fp16, feature pairs (128B/row)
__device__ __align__(16) __half2 g_h2h[NN * 32];  // h2, fp16
__device__ __align__(16) float g_as1[NN * 4];
__device__ __align__(16) float g_ad1[NN * 4];
__device__ __align__(16) float g_agg1[NN * HID];
__device__ __align__(16) float g_as2[NN];
__device__ __align__(16) float g_ad2[NN];
__device__ int g_cnt[NN];    // degree by dst (zero at load; re-zeroed by agg2f each call)
__device__ int g_rs[NN];     // CSR row starts (unordered ranges)
__device__ int g_cur[NN];    // fill cursors
__device__ int g_srcs[EE];   // CSR: src per incident edge, grouped by dst
__device__ int g_total;      // range-allocation cursor (reset by k_fill each call)

__device__ __forceinline__ float lrelu(float t) { return fmaxf(t, 0.2f * t); }

// forced (non-hoistable) 16B global load
__device__ __forceinline__ float4 ldg128_volatile(const float* p) {
    float4 r;
    asm volatile("ld.global.nc.v4.f32 {%0,%1,%2,%3}, [%4];"
                 : "=f"(r.x), "=f"(r.y), "=f"(r.z), "=f"(r.w) : "l"(p));
    return r;
}

// ---------------- layer-1 GEMM (+ fused degree histogram), split-K warp pairs ----------------
// 256 threads = 8 warps = 4 pairs. Pair p owns 8 rows; warp half h covers k in [64h, 64h+64).
// Partial accs combined via smem (aliased over X staging), epilogue on even warps.
__global__ void k_gemm1h(const float* __restrict__ x, const float* __restrict__ W1,
                         const float* __restrict__ a_src, const float* __restrict__ a_dst,
                         const int* __restrict__ ei) {
    __shared__ float2 Wsh[FIN * 32];                 // 32 KB
    __shared__ __align__(16) float Xbuf[4096];       // 16 KB: X staging, then combine buffer
    int tid = threadIdx.x;

    // fused histogram: exactly 2 edges per thread (3125*512 == EE)
    {
        int e = blockIdx.x * 512 + tid;
        atomicAdd(&g_cnt[__ldg(&ei[EE + e])], 1);
        atomicAdd(&g_cnt[__ldg(&ei[EE + e + 256])], 1);
    }

    for (int i = tid; i < FIN * 32; i += 256) Wsh[i] = ((const float2*)W1)[i];

    int lane = tid & 31, w = tid >> 5;
    int p = w >> 1, half = w & 1;
    int r0 = (blockIdx.x * 4 + p) * 8;

    float4* X = (float4*)Xbuf;   // X[(p*FIN + k)*2 + i] : rows r0..r0+3 (i=0), r0+4..r0+7 (i=1)
#pragma unroll
    for (int kk = 0; kk < 2; kk++) {
        int k = half * 64 + kk * 32 + lane;
        float4 va, vb;
        va.x = x[(r0 + 0) * FIN + k];
        va.y = x[(r0 + 1) * FIN + k];
        va.z = x[(r0 + 2) * FIN + k];
        va.w = x[(r0 + 3) * FIN + k];
        vb.x = x[(r0 + 4) * FIN + k];
        vb.y = x[(r0 + 5) * FIN + k];
        vb.z = x[(r0 + 6) * FIN + k];
        vb.w = x[(r0 + 7) * FIN + k];
        X[(p * FIN + k) * 2 + 0] = va;
        X[(p * FIN + k) * 2 + 1] = vb;
    }
    __syncthreads();

    float acc0[8] = {}, acc1[8] = {};
    int kbase = half * 64;
#pragma unroll 16
    for (int kk = 0; kk < 64; kk++) {
        int k = kbase + kk;
        float4 xa = X[(p * FIN + k) * 2 + 0];
        float4 xb = X[(p * FIN + k) * 2 + 1];
        float2 wv = Wsh[k * 32 + lane];
        acc0[0] += xa.x * wv.x;  acc1[0] += xa.x * wv.y;
        acc0[1] += xa.y * wv.x;  acc1[1] += xa.y * wv.y;
        acc0[2] += xa.z * wv.x;  acc1[2] += xa.z * wv.y;
        acc0[3] += xa.w * wv.x;  acc1[3] += xa.w * wv.y;
        acc0[4] += xb.x * wv.x;  acc1[4] += xb.x * wv.y;
        acc0[5] += xb.y * wv.x;  acc1[5] += xb.y * wv.y;
        acc0[6] += xb.z * wv.x;  acc1[6] += xb.z * wv.y;
        acc0[7] += xb.w * wv.x;  acc1[7] += xb.w * wv.y;
    }
    __syncthreads();   // X staging no longer needed; reuse as combine buffer

    float* Cb = Xbuf;  // Cb[(p*16 + j)*32 + lane]
    if (half == 1) {
#pragma unroll
        for (int j = 0; j < 8; j++) {
            Cb[(p * 16 + j) * 32 + lane] = acc0[j];
            Cb[(p * 16 + 8 + j) * 32 + lane] = acc1[j];
        }
    }
    __syncthreads();

    if (half == 0) {
#pragma unroll
        for (int j = 0; j < 8; j++) {
            acc0[j] += Cb[(p * 16 + j) * 32 + lane];
            acc1[j] += Cb[(p * 16 + 8 + j) * 32 + lane];
        }
        float s0 = __ldg(&a_src[2 * lane]), s1 = __ldg(&a_src[2 * lane + 1]);
        float d0 = __ldg(&a_dst[2 * lane]), d1 = __ldg(&a_dst[2 * lane + 1]);
#pragma unroll
        for (int i = 0; i < 8; i++) {
            int row = r0 + i;
            g_h1h[row * 32 + lane] = __floats2half2_rn(acc0[i], acc1[i]);
            float pa = acc0[i] * s0 + acc1[i] * s1;
            float pd = acc0[i] * d0 + acc1[i] * d1;
#pragma unroll
            for (int off = 4; off; off >>= 1) {
                pa += __shfl_xor_sync(0xffffffffu, pa, off);
                pd += __shfl_xor_sync(0xffffffffu, pd, off);
            }
            if ((lane & 7) == 0) {
                g_as1[row * 4 + (lane >> 3)] = pa;
                g_ad1[row * 4 + (lane >> 3)] = pd;
            }
        }
    }
}

// ---------------- CSR range allocation ----------------
__global__ void k_alloc() {
    int i = blockIdx.x * blockDim.x + threadIdx.x;
    int lane = threadIdx.x & 31;
    int c = (i < NN) ? g_cnt[i] : 0;
    int s = c;
#pragma unroll
    for (int off = 1; off < 32; off <<= 1) {
        int t = __shfl_up_sync(0xffffffffu, s, off);
        if (lane >= off) s += t;
    }
    int wtot = __shfl_sync(0xffffffffu, s, 31);
    int base = 0;
    if (lane == 31) base = atomicAdd(&g_total, wtot);
    base = __shfl_sync(0xffffffffu, base, 31);
    if (i < NN) {
        int r = base + s - c;
        g_rs[i] = r;
        g_cur[i] = r;
    }
}

__global__ void k_fill(const int* __restrict__ ei) {
    int e = blockIdx.x * blockDim.x + threadIdx.x;
    if (e == 0) g_total = 0;
    if (e < EE) {
        int s = __ldg(&ei[e]);
        int d = __ldg(&ei[EE + e]);
        int p = atomicAdd(&g_cur[d], 1);
        g_srcs[p] = s;
    }
}

// ---------------- layer-1 gather aggregation: node-strided warps ----------------
__global__ void k_agg1() {
    int lane = threadIdx.x & 31;
    int grp = lane >> 3;
    int q = lane & 7;
    int head = q >> 1;
    int wglob = blockIdx.x * 8 + (threadIdx.x >> 5);
    const int nwarps = 1250 * 8;

    const float4* h4 = (const float4*)g_h1h;

    for (int n = wglob; n < NN; n += nwarps) {
        int rs = g_rs[n];
        int deg = g_cnt[n];
        float adv = g_ad1[n * 4 + head];

        float a0 = 0.f, a1 = 0.f, a2 = 0.f, a3 = 0.f;
        float a4 = 0.f, a5 = 0.f, a6 = 0.f, a7 = 0.f, den = 0.f;

        for (int j = 0; j < deg; j += 8) {
            int j0 = j + grp, j1 = j + grp + 4;
            int s0 = g_srcs[rs + (j0 < deg ? j0 : deg - 1)];
            int s1 = g_srcs[rs + (j1 < deg ? j1 : deg - 1)];
            float c0 = g_as1[s0 * 4 + head];
            float c1 = g_as1[s1 * 4 + head];
            float4 r0 = h4[s0 * 8 + q];
            float4 r1 = h4[s1 * 8 + q];
            float e0 = (j0 < deg) ? __expf(lrelu(c0 + adv)) : 0.f;
            float e1 = (j1 < deg) ? __expf(lrelu(c1 + adv)) : 0.f;
            den += e0 + e1;
            const __half2* p0 = (const __half2*)&r0;
            const __half2* p1 = (const __half2*)&r1;
            float2 v;
            v = __half22float2(p0[0]); a0 += e0 * v.x; a1 += e0 * v.y;
            v = __half22float2(p0[1]); a2 += e0 * v.x; a3 += e0 * v.y;
            v = __half22float2(p0[2]); a4 += e0 * v.x; a5 += e0 * v.y;
            v = __half22float2(p0[3]); a6 += e0 * v.x; a7 += e0 * v.y;
            v = __half22float2(p1[0]); a0 += e1 * v.x; a1 += e1 * v.y;
            v = __half22float2(p1[1]); a2 += e1 * v.x; a3 += e1 * v.y;
            v = __half22float2(p1[2]); a4 += e1 * v.x; a5 += e1 * v.y;
            v = __half22float2(p1[3]); a6 += e1 * v.x; a7 += e1 * v.y;
        }
#pragma unroll
        for (int off = 8; off <= 16; off <<= 1) {
            den += __shfl_xor_sync(0xffffffffu, den, off);
            a0 += __shfl_xor_sync(0xffffffffu, a0, off);
            a1 += __shfl_xor_sync(0xffffffffu, a1, off);
            a2 += __shfl_xor_sync(0xffffffffu, a2, off);
            a3 += __shfl_xor_sync(0xffffffffu, a3, off);
            a4 += __shfl_xor_sync(0xffffffffu, a4, off);
            a5 += __shfl_xor_sync(0xffffffffu, a5, off);
            a6 += __shfl_xor_sync(0xffffffffu, a6, off);
            a7 += __shfl_xor_sync(0xffffffffu, a7, off);
        }
        float inv = 1.f / (den + 1e-16f);
        if (grp == 0) {
            float4* dst = (float4*)g_agg1 + n * 16 + q * 2;
            float4 o;
            o.x = a0 * inv; o.y = a1 * inv; o.z = a2 * inv; o.w = a3 * inv;
            dst[0] = o;
            o.x = a4 * inv; o.y = a5 * inv; o.z = a6 * inv; o.w = a7 * inv;
            dst[1] = o;
        }
    }
}

// ---------------- layer-2 GEMM: split-K warp pairs ----------------
__global__ void k_gemm2(const float* __restrict__ W2, const float* __restrict__ b1,
                        const float* __restrict__ a_src, const float* __restrict__ a_dst) {
    __shared__ float2 Wsh[HID * 32];                 // 16 KB
    __shared__ __align__(16) float Xbuf[2048];       // 8 KB: X staging, then combine buffer
    int tid = threadIdx.x;
    for (int i = tid; i < HID * 32; i += 256) Wsh[i] = ((const float2*)W2)[i];

    int lane = tid & 31, w = tid >> 5;
    int p = w >> 1, half = w & 1;
    int r0 = (blockIdx.x * 4 + p) * 8;

    float4* X = (float4*)Xbuf;   // X[(p*HID + k)*2 + i]
    {
        int k = half * 32 + lane;      // each lane one k in its warp's half
        float bk = __ldg(&b1[k]);
        float4 va, vb;
        va.x = fmaxf(g_agg1[(r0 + 0) * HID + k] + bk, 0.f);
        va.y = fmaxf(g_agg1[(r0 + 1) * HID + k] + bk, 0.f);
        va.z = fmaxf(g_agg1[(r0 + 2) * HID + k] + bk, 0.f);
        va.w = fmaxf(g_agg1[(r0 + 3) * HID + k] + bk, 0.f);
        vb.x = fmaxf(g_agg1[(r0 + 4) * HID + k] + bk, 0.f);
        vb.y = fmaxf(g_agg1[(r0 + 5) * HID + k] + bk, 0.f);
        vb.z = fmaxf(g_agg1[(r0 + 6) * HID + k] + bk, 0.f);
        vb.w = fmaxf(g_agg1[(r0 + 7) * HID + k] + bk, 0.f);
        X[(p * HID + k) * 2 + 0] = va;
        X[(p * HID + k) * 2 + 1] = vb;
    }
    __syncthreads();

    float acc0[8] = {}, acc1[8] = {};
    int kbase = half * 32;
#pragma unroll 8
    for (int kk = 0; kk < 32; kk++) {
        int k = kbase + kk;
        float4 xa = X[(p * HID + k) * 2 + 0];
        float4 xb = X[(p * HID + k) * 2 + 1];
        float2 wv = Wsh[k * 32 + lane];
        acc0[0] += xa.x * wv.x;  acc1[0] += xa.x * wv.y;
        acc0[1] += xa.y * wv.x;  acc1[1] += xa.y * wv.y;
        acc0[2] += xa.z * wv.x;  acc1[2] += xa.z * wv.y;
        acc0[3] += xa.w * wv.x;  acc1[3] += xa.w * wv.y;
        acc0[4] += xb.x * wv.x;  acc1[4] += xb.x * wv.y;
        acc0[5] += xb.y * wv.x;  acc1[5] += xb.y * wv.y;
        acc0[6] += xb.z * wv.x;  acc1[6] += xb.z * wv.y;
        acc0[7] += xb.w * wv.x;  acc1[7] += xb.w * wv.y;
    }
    __syncthreads();

    float* Cb = Xbuf;  // Cb[(p*16 + j)*32 + lane]
    if (half == 1) {
#pragma unroll
        for (int j = 0; j < 8; j++) {
            Cb[(p * 16 + j) * 32 + lane] = acc0[j];
            Cb[(p * 16 + 8 + j) * 32 + lane] = acc1[j];
        }
    }
    __syncthreads();

    if (half == 0) {
#pragma unroll
        for (int j = 0; j < 8; j++) {
            acc0[j] += Cb[(p * 16 + j) * 32 + lane];
            acc1[j] += Cb[(p * 16 + 8 + j) * 32 + lane];
        }
        float s0 = __ldg(&a_src[2 * lane]), s1 = __ldg(&a_src[2 * lane + 1]);
        float d0 = __ldg(&a_dst[2 * lane]), d1 = __ldg(&a_dst[2 * lane + 1]);
#pragma unroll
        for (int i = 0; i < 8; i++) {
            int row = r0 + i;
            g_h2h[row * 32 + lane] = __floats2half2_rn(acc0[i], acc1[i]);
            float pa = acc0[i] * s0 + acc1[i] * s1;
            float pd = acc0[i] * d0 + acc1[i] * d1;
#pragma unroll
            for (int off = 16; off; off >>= 1) {
                pa += __shfl_xor_sync(0xffffffffu, pa, off);
                pd += __shfl_xor_sync(0xffffffffu, pd, off);
            }
            if (lane == 0) {
                g_as2[row] = pa;
                g_ad2[row] = pd;
            }
        }
    }
}

// ---------------- layer-2 gather aggregation + projection: node-strided warps ----------------
__global__ void k_agg2f(const float* __restrict__ b2, const float* __restrict__ Wc,
                        const float* __restrict__ bc, float* __restrict__ out) {
    int lane = threadIdx.x & 31;
    int grp = lane >> 3;
    int q = lane & 7;
    int wglob = blockIdx.x * 8 + (threadIdx.x >> 5);
    const int nwarps = 1250 * 8;

    const float4* h4 = (const float4*)g_h2h;

    for (int n = wglob; n < NN; n += nwarps) {
        int rs = g_rs[n];
        int deg = g_cnt[n];
        float adv = g_ad2[n];

        float a0 = 0.f, a1 = 0.f, a2 = 0.f, a3 = 0.f;
        float a4 = 0.f, a5 = 0.f, a6 = 0.f, a7 = 0.f, den = 0.f;

        for (int j = 0; j < deg; j += 8) {
            int j0 = j + grp, j1 = j + grp + 4;
            int s0 = g_srcs[rs + (j0 < deg ? j0 : deg - 1)];
            int s1 = g_srcs[rs + (j1 < deg ? j1 : deg - 1)];
            float c0 = g_as2[s0];
            float c1 = g_as2[s1];
            float4 r0 = h4[s0 * 8 + q];
            float4 r1 = h4[s1 * 8 + q];
            float e0 = (j0 < deg) ? __expf(lrelu(c0 + adv)) : 0.f;
            float e1 = (j1 < deg) ? __expf(lrelu(c1 + adv)) : 0.f;
            den += e0 + e1;
            const __half2* p0 = (const __half2*)&r0;
            const __half2* p1 = (const __half2*)&r1;
            float2 v;
            v = __half22float2(p0[0]); a0 += e0 * v.x; a1 += e0 * v.y;
            v = __half22float2(p0[1]); a2 += e0 * v.x; a3 += e0 * v.y;
            v = __half22float2(p0[2]); a4 += e0 * v.x; a5 += e0 * v.y;
            v = __half22float2(p0[3]); a6 += e0 * v.x; a7 += e0 * v.y;
            v = __half22float2(p1[0]); a0 += e1 * v.x; a1 += e1 * v.y;
            v = __half22float2(p1[1]); a2 += e1 * v.x; a3 += e1 * v.y;
            v = __half22float2(p1[2]); a4 += e1 * v.x; a5 += e1 * v.y;
            v = __half22float2(p1[3]); a6 += e1 * v.x; a7 += e1 * v.y;
        }
#pragma unroll
        for (int off = 8; off <= 16; off <<= 1) {
            den += __shfl_xor_sync(0xffffffffu, den, off);
            a0 += __shfl_xor_sync(0xffffffffu, a0, off);
            a1 += __shfl_xor_sync(0xffffffffu, a1, off);
            a2 += __shfl_xor_sync(0xffffffffu, a2, off);
            a3 += __shfl_xor_sync(0xffffffffu, a3, off);
            a4 += __shfl_xor_sync(0xffffffffu, a4, off);
            a5 += __shfl_xor_sync(0xffffffffu, a5, off);
            a6 += __shfl_xor_sync(0xffffffffu, a6, off);
            a7 += __shfl_xor_sync(0xffffffffu, a7, off);
        }
        float inv = 1.f / (den + 1e-16f);
        float4 ba = ldg128_volatile(b2 + q * 8);
        float4 bb = ldg128_volatile(b2 + q * 8 + 4);
        float4 wa = ldg128_volatile(Wc + q * 8);
        float4 wb = ldg128_volatile(Wc + q * 8 + 4);
        float v = fmaxf(a0 * inv + ba.x, 0.f) * wa.x
                + fmaxf(a1 * inv + ba.y, 0.f) * wa.y
                + fmaxf(a2 * inv + ba.z, 0.f) * wa.z
                + fmaxf(a3 * inv + ba.w, 0.f) * wa.w
                + fmaxf(a4 * inv + bb.x, 0.f) * wb.x
                + fmaxf(a5 * inv + bb.y, 0.f) * wb.y
                + fmaxf(a6 * inv + bb.z, 0.f) * wb.z
                + fmaxf(a7 * inv + bb.w, 0.f) * wb.w;
#pragma unroll
        for (int off = 1; off <= 4; off <<= 1) v += __shfl_xor_sync(0xffffffffu, v, off);
        if (lane == 0) {
            out[n] = v + __ldg(&bc[0]);
            g_cnt[n] = 0;  // restore invariant for next call's histogram
        }
    }
}

extern "C" void kernel_launch(void* const* d_in, const int* in_sizes, int n_in,
                              void* d_out, int out_size) {
    const float* x      = (const float*)d_in[0];
    const int* ei       = (const int*)d_in[1];   // JAX x64 disabled -> int32
    const float* W1     = (const float*)d_in[2];
    const float* a_src1 = (const float*)d_in[3];
    const float* a_dst1 = (const float*)d_in[4];
    const float* b1     = (const float*)d_in[5];
    const float* W2     = (const float*)d_in[6];
    const float* a_src2 = (const float*)d_in[7];
    const float* a_dst2 = (const float*)d_in[8];
    const float* b2     = (const float*)d_in[9];
    const float* Wc     = (const float*)d_in[10];
    const float* bc     = (const float*)d_in[11];
    float* out          = (float*)d_out;
    (void)in_sizes; (void)n_in; (void)out_size;

    k_gemm1h<<<3125, 256>>>(x, W1, a_src1, a_dst1, ei);  // 1: GEMM1 + degree hist
    k_alloc<<<(NN + 255) / 256, 256>>>();                // 2: CSR range alloc
    k_fill<<<(EE + 255) / 256, 256>>>(ei);               // 3: CSR fill
    k_agg1<<<1250, 256>>>();                             // 4: <- ncu sample
    k_gemm2<<<3125, 256>>>(W2, b1, a_src2, a_dst2);      // 5
    k_agg2f<<<1250, 256>>>(b2, Wc, bc, out);             // 6
}